// round 3
// baseline (speedup 1.0000x reference)
#include <cuda_runtime.h>
#include <cuda_bf16.h>

#define NMAX 50000
#define EMAX 1000000
#define HD   128

// ---------------- device scratch (no allocation allowed) ----------------
__device__ __align__(16) float g_bufA[NMAX * HD];     // activations x
__device__ __align__(16) float g_bufB[NMAX * HD];     // pre-scaled messages hs
__device__ __align__(16) float g_s1[NMAX * 3 + 4];
__device__ __align__(16) float g_s2[NMAX * 3 + 4];
__device__ __align__(16) float g_dis[NMAX];
__device__ __align__(16) int   g_deg[NMAX];
__device__ __align__(16) int   g_rowptr[NMAX + 1];
__device__ __align__(16) int   g_cursor[NMAX];
__device__ __align__(16) int   g_col[EMAX];
__device__ __align__(16) int   g_src[EMAX];
__device__ __align__(16) int   g_dst[EMAX];
__device__ __align__(16) int   g_bsum[64];
__device__ int g_is64;

// ---------------- edge dtype detection + canonicalization ----------------
// If edge_index is int64 (little-endian, values < 2^31), every odd 32-bit word
// of the src region is 0. If int32, odd words are random node ids.
__global__ void k_detect(const int* __restrict__ w, int E) {
    if (blockIdx.x == 0 && threadIdx.x == 0) {
        int orv = 0;
        int lim = 2 * E;                 // stay inside int32 interpretation
        for (int i = 1; i < 2048 && i < lim; i += 2) orv |= w[i];
        g_is64 = (orv == 0) ? 1 : 0;
    }
}

__global__ void k_convert(const int* __restrict__ w, int E) {
    int i = blockIdx.x * blockDim.x + threadIdx.x;
    if (i >= E) return;
    if (g_is64) {
        g_src[i] = w[2 * i];
        g_dst[i] = w[2 * E + 2 * i];
    } else {
        g_src[i] = w[i];
        g_dst[i] = w[E + i];
    }
}

// ---------------- preprocessing: degree, dis, CSR ----------------
__global__ void k_deg_zero(int n) {
    int i = blockIdx.x * blockDim.x + threadIdx.x;
    if (i < n) g_deg[i] = 0;
}

__global__ void k_count(int E) {
    int i = blockIdx.x * blockDim.x + threadIdx.x;
    if (i < E) atomicAdd(&g_deg[g_dst[i]], 1);
}

// block-wise inclusive scan of deg -> rowptr[i+1] (pre-offset), block sums, dis
__global__ void k_scan1(int n) {
    __shared__ int s[1024];
    int i = blockIdx.x * 1024 + threadIdx.x;
    int v = (i < n) ? g_deg[i] : 0;
    if (i < n) g_dis[i] = rsqrtf((float)(v + 1));   // +1 self loop
    s[threadIdx.x] = v;
    __syncthreads();
    for (int off = 1; off < 1024; off <<= 1) {
        int t = (threadIdx.x >= off) ? s[threadIdx.x - off] : 0;
        __syncthreads();
        s[threadIdx.x] += t;
        __syncthreads();
    }
    if (i < n) g_rowptr[i + 1] = s[threadIdx.x];
    if (threadIdx.x == 1023) g_bsum[blockIdx.x] = s[1023];
}

__global__ void k_scan2(int nb) {
    if (threadIdx.x == 0 && blockIdx.x == 0) {
        int acc = 0;
        for (int b = 0; b < nb; b++) { int t = g_bsum[b]; g_bsum[b] = acc; acc += t; }
    }
}

__global__ void k_scan3(int n) {
    int i = blockIdx.x * 1024 + threadIdx.x;
    if (i < n) g_rowptr[i + 1] += g_bsum[blockIdx.x];
    if (i == 0) g_rowptr[0] = 0;
}

__global__ void k_cursor(int n) {
    int i = blockIdx.x * blockDim.x + threadIdx.x;
    if (i < n) g_cursor[i] = g_rowptr[i];
}

__global__ void k_fill(int E) {
    int i = blockIdx.x * blockDim.x + threadIdx.x;
    if (i < E) {
        int p = atomicAdd(&g_cursor[g_dst[i]], 1);
        g_col[p] = g_src[i];
    }
}

// ---------------- 3-wide ops (layer 0 input side, layer 4 output side) ----
__global__ void k_scale3(const float* __restrict__ in, float* __restrict__ out, int n) {
    int i = blockIdx.x * blockDim.x + threadIdx.x;
    if (i < n * 3) out[i] = in[i] * g_dis[i / 3];
}

// out[n][j] = dis[n] * (in[n][j] + sum_{e into n} in[src][j])  (+ bias)
__global__ void k_agg3(const float* __restrict__ in, float* __restrict__ out,
                       const float* __restrict__ bias, int n) {
    int node = blockIdx.x * blockDim.x + threadIdx.x;
    if (node >= n) return;
    float a0 = in[node * 3 + 0], a1 = in[node * 3 + 1], a2 = in[node * 3 + 2];
    int s = g_rowptr[node], e = g_rowptr[node + 1];
    for (int i = s; i < e; i++) {
        int c = g_col[i];
        a0 += in[c * 3 + 0];
        a1 += in[c * 3 + 1];
        a2 += in[c * 3 + 2];
    }
    float d = g_dis[node];
    a0 *= d; a1 *= d; a2 *= d;
    if (bias) { a0 += bias[0]; a1 += bias[1]; a2 += bias[2]; }
    out[node * 3 + 0] = a0;
    out[node * 3 + 1] = a1;
    out[node * 3 + 2] = a2;
}

// x = silu(t3 @ W0 + b0), t3 = S*pos
__global__ void k_gemm_in(const float* __restrict__ t3, const float* __restrict__ W0,
                          const float* __restrict__ b0, float* __restrict__ out, int n) {
    __shared__ float sw[3 * HD];
    __shared__ float sb[HD];
    int t = threadIdx.x;
    for (int i = t; i < 3 * HD; i += blockDim.x) sw[i] = W0[i];
    if (t < HD) sb[t] = b0[t];
    __syncthreads();
    int gid = blockIdx.x * blockDim.x + t;
    if (gid < n * HD) {
        int node = gid >> 7, j = gid & 127;
        float p0 = t3[node * 3 + 0], p1 = t3[node * 3 + 1], p2 = t3[node * 3 + 2];
        float v = p0 * sw[j] + p1 * sw[HD + j] + p2 * sw[2 * HD + j] + sb[j];
        out[gid] = v / (1.0f + __expf(-v));
    }
}

// hs3 = (x @ W4) * dis   (warp per node)
__global__ void k_gemm_out(const float* __restrict__ X, const float* __restrict__ W4,
                           float* __restrict__ Hs, int n) {
    int warp = (blockIdx.x * blockDim.x + threadIdx.x) >> 5;
    int lane = threadIdx.x & 31;
    if (warp >= n) return;
    float4 x = ((const float4*)X)[warp * 32 + lane];
    int k = lane * 4;
    float a0 = x.x * W4[(k + 0) * 3 + 0] + x.y * W4[(k + 1) * 3 + 0] +
               x.z * W4[(k + 2) * 3 + 0] + x.w * W4[(k + 3) * 3 + 0];
    float a1 = x.x * W4[(k + 0) * 3 + 1] + x.y * W4[(k + 1) * 3 + 1] +
               x.z * W4[(k + 2) * 3 + 1] + x.w * W4[(k + 3) * 3 + 1];
    float a2 = x.x * W4[(k + 0) * 3 + 2] + x.y * W4[(k + 1) * 3 + 2] +
               x.z * W4[(k + 2) * 3 + 2] + x.w * W4[(k + 3) * 3 + 2];
    for (int off = 16; off; off >>= 1) {
        a0 += __shfl_xor_sync(0xFFFFFFFF, a0, off);
        a1 += __shfl_xor_sync(0xFFFFFFFF, a1, off);
        a2 += __shfl_xor_sync(0xFFFFFFFF, a2, off);
    }
    if (lane == 0) {
        float d = g_dis[warp];
        Hs[warp * 3 + 0] = a0 * d;
        Hs[warp * 3 + 1] = a1 * d;
        Hs[warp * 3 + 2] = a2 * d;
    }
}

// ---------------- hidden-layer GEMM: H = (X @ W) * dis ----------------
// 128x128 tile per block, 256 threads, 8x8 per thread, K tiled by 16.
__global__ __launch_bounds__(256) void k_gemm128(const float* __restrict__ X,
                                                 const float* __restrict__ W,
                                                 float* __restrict__ Hout, int nrows) {
    __shared__ __align__(16) float sX[16][128];
    __shared__ __align__(16) float sW[16][128];
    int m0 = blockIdx.x * 128;
    int t = threadIdx.x;
    int tx = t & 15;   // col group -> cols tx*8..+7
    int ty = t >> 4;   // row group -> rows ty*8..+7
    float acc[8][8];
#pragma unroll
    for (int i = 0; i < 8; i++)
#pragma unroll
        for (int j = 0; j < 8; j++) acc[i][j] = 0.0f;

    for (int k0 = 0; k0 < HD; k0 += 16) {
#pragma unroll
        for (int l = 0; l < 2; l++) {
            int idx = t + l * 256;       // 0..511
            int row = idx >> 2;          // 0..127
            int kq = idx & 3;
            int gr = m0 + row;
            float4 v = make_float4(0.f, 0.f, 0.f, 0.f);
            if (gr < nrows) v = *(const float4*)(X + gr * HD + k0 + kq * 4);
            sX[kq * 4 + 0][row] = v.x;
            sX[kq * 4 + 1][row] = v.y;
            sX[kq * 4 + 2][row] = v.z;
            sX[kq * 4 + 3][row] = v.w;
        }
#pragma unroll
        for (int l = 0; l < 2; l++) {
            int idx = t + l * 256;
            int kr = idx >> 5;           // 0..15
            int c4 = idx & 31;           // 0..31
            *(float4*)(&sW[kr][c4 * 4]) = *(const float4*)(W + (k0 + kr) * HD + c4 * 4);
        }
        __syncthreads();
#pragma unroll
        for (int kk = 0; kk < 16; kk++) {
            float a[8], b[8];
            *(float4*)(a)     = *(float4*)(&sX[kk][ty * 8]);
            *(float4*)(a + 4) = *(float4*)(&sX[kk][ty * 8 + 4]);
            *(float4*)(b)     = *(float4*)(&sW[kk][tx * 8]);
            *(float4*)(b + 4) = *(float4*)(&sW[kk][tx * 8 + 4]);
#pragma unroll
            for (int i = 0; i < 8; i++)
#pragma unroll
                for (int j = 0; j < 8; j++) acc[i][j] += a[i] * b[j];
        }
        __syncthreads();
    }
#pragma unroll
    for (int i = 0; i < 8; i++) {
        int row = m0 + ty * 8 + i;
        if (row < nrows) {
            float d = g_dis[row];
            float4 o0 = make_float4(acc[i][0] * d, acc[i][1] * d, acc[i][2] * d, acc[i][3] * d);
            float4 o1 = make_float4(acc[i][4] * d, acc[i][5] * d, acc[i][6] * d, acc[i][7] * d);
            *(float4*)(Hout + row * HD + tx * 8)     = o0;
            *(float4*)(Hout + row * HD + tx * 8 + 4) = o1;
        }
    }
}

// ---------------- 128-wide aggregation: warp per node ----------------
// out[n] = silu( dis[n]*(hs[n] + sum hs[src]) + b )
__global__ void k_agg128(const float* __restrict__ hs, const float* __restrict__ bias,
                         float* __restrict__ out, int n) {
    int warp = (blockIdx.x * blockDim.x + threadIdx.x) >> 5;
    int lane = threadIdx.x & 31;
    if (warp >= n) return;
    const float4* hs4 = (const float4*)hs;
    float4 acc = hs4[warp * 32 + lane];   // self loop (hs = h*dis)
    int s = g_rowptr[warp], e = g_rowptr[warp + 1];
    int i = s;
    for (; i + 4 <= e; i += 4) {
        int c0 = g_col[i], c1 = g_col[i + 1], c2 = g_col[i + 2], c3 = g_col[i + 3];
        float4 v0 = hs4[c0 * 32 + lane];
        float4 v1 = hs4[c1 * 32 + lane];
        float4 v2 = hs4[c2 * 32 + lane];
        float4 v3 = hs4[c3 * 32 + lane];
        acc.x += v0.x + v1.x + v2.x + v3.x;
        acc.y += v0.y + v1.y + v2.y + v3.y;
        acc.z += v0.z + v1.z + v2.z + v3.z;
        acc.w += v0.w + v1.w + v2.w + v3.w;
    }
    for (; i < e; i++) {
        int c = g_col[i];
        float4 v = hs4[c * 32 + lane];
        acc.x += v.x; acc.y += v.y; acc.z += v.z; acc.w += v.w;
    }
    float d = g_dis[warp];
    float4 b = ((const float4*)bias)[lane];
    float4 r;
    r.x = acc.x * d + b.x;
    r.y = acc.y * d + b.y;
    r.z = acc.z * d + b.z;
    r.w = acc.w * d + b.w;
    r.x = r.x / (1.0f + __expf(-r.x));
    r.y = r.y / (1.0f + __expf(-r.y));
    r.z = r.z / (1.0f + __expf(-r.z));
    r.w = r.w / (1.0f + __expf(-r.w));
    ((float4*)out)[warp * 32 + lane] = r;
}

// ---------------- host launch ----------------
extern "C" void kernel_launch(void* const* d_in, const int* in_sizes, int n_in,
                              void* d_out, int out_size) {
    const float* pos = (const float*)d_in[0];
    const int* ei_words = (const int*)d_in[1];   // int32 view; dtype detected on device
    const float* W[5]; const float* B[5];
    for (int l = 0; l < 5; l++) {
        W[l] = (const float*)d_in[2 + 2 * l];
        B[l] = (const float*)d_in[3 + 2 * l];
    }
    int N = in_sizes[0] / 3;        // 50000
    int E = in_sizes[1] / 2;        // 1000000

    float *bufA, *bufB, *s1, *s2;
    cudaGetSymbolAddress((void**)&bufA, g_bufA);
    cudaGetSymbolAddress((void**)&bufB, g_bufB);
    cudaGetSymbolAddress((void**)&s1, g_s1);
    cudaGetSymbolAddress((void**)&s2, g_s2);

    int NB = (N + 1023) / 1024;

    // canonicalize edges (handles int32 or int64 edge_index)
    k_detect<<<1, 32>>>(ei_words, E);
    k_convert<<<(E + 255) / 256, 256>>>(ei_words, E);

    // preprocessing: degrees, dis, CSR
    k_deg_zero<<<(N + 255) / 256, 256>>>(N);
    k_count<<<(E + 255) / 256, 256>>>(E);
    k_scan1<<<NB, 1024>>>(N);
    k_scan2<<<1, 32>>>(NB);
    k_scan3<<<NB, 1024>>>(N);
    k_cursor<<<NB, 1024>>>(N);
    k_fill<<<(E + 255) / 256, 256>>>(E);

    // layer 0: aggregate pos (3-wide) first, then dense W0 + bias + silu
    k_scale3<<<(3 * N + 255) / 256, 256>>>(pos, s1, N);
    k_agg3<<<(N + 255) / 256, 256>>>(s1, s2, nullptr, N);
    k_gemm_in<<<(N * HD + 255) / 256, 256>>>(s2, W[0], B[0], bufA, N);

    // layers 1..3: GEMM (scaled) then 128-wide aggregation + bias + silu
    int gemm_blocks = (N + 127) / 128;
    int agg_blocks = (N * 32 + 255) / 256;
    for (int l = 1; l <= 3; l++) {
        k_gemm128<<<gemm_blocks, 256>>>(bufA, W[l], bufB, N);
        k_agg128<<<agg_blocks, 256>>>(bufB, B[l], bufA, N);
    }

    // layer 4: dense to 3-wide first, then 3-wide aggregation + bias
    k_gemm_out<<<agg_blocks, 256>>>(bufA, W[4], s1, N);
    k_agg3<<<(N + 255) / 256, 256>>>(s1, (float*)d_out, B[4], N);
}

// round 4
// speedup vs baseline: 1.1619x; 1.1619x over previous
#include <cuda_runtime.h>
#include <cuda_fp16.h>
#include <mma.h>

using namespace nvcuda;

#define NMAX 50000
#define NPAD 50176          // 392*128, padded so last GEMM tile stays in-bounds
#define EMAX 1000000
#define HD   128

// ---------------- device scratch (no allocation allowed) ----------------
__device__ __align__(16) float g_bufA[NPAD * HD];     // activations x (padding stays 0)
__device__ __align__(16) float g_bufB[NPAD * HD];     // pre-scaled messages hs
__device__ __align__(16) float g_s1[NMAX * 3 + 4];
__device__ __align__(16) float g_s2[NMAX * 3 + 4];
__device__ __align__(16) float g_dis[NPAD];           // padding stays 0
__device__ __align__(16) int   g_deg[NMAX];
__device__ __align__(16) int   g_rowptr[NMAX + 1];
__device__ __align__(16) int   g_cursor[NMAX];
__device__ __align__(16) int   g_col[EMAX];
__device__ __align__(16) int   g_src[EMAX];
__device__ __align__(16) int   g_dst[EMAX];
__device__ __align__(16) int   g_bsum[64];
__device__ int g_is64;

// ---------------- edge dtype detection + canonicalization ----------------
__global__ void k_detect(const int* __restrict__ w, int E) {
    if (blockIdx.x == 0 && threadIdx.x == 0) {
        int orv = 0;
        int lim = 2 * E;
        for (int i = 1; i < 2048 && i < lim; i += 2) orv |= w[i];
        g_is64 = (orv == 0) ? 1 : 0;
    }
}

__global__ void k_deg_zero(int n) {
    int i = blockIdx.x * blockDim.x + threadIdx.x;
    if (i < n) g_deg[i] = 0;
}

// convert + degree count fused (one pass over edge data)
__global__ void k_convert(const int* __restrict__ w, int E) {
    int i = blockIdx.x * blockDim.x + threadIdx.x;
    if (i >= E) return;
    int s, d;
    if (g_is64) {
        s = w[2 * i];
        d = w[2 * E + 2 * i];
    } else {
        s = w[i];
        d = w[E + i];
    }
    g_src[i] = s;
    g_dst[i] = d;
    atomicAdd(&g_deg[d], 1);
}

// ---------------- CSR build ----------------
__global__ void k_scan1(int n) {
    __shared__ int s[1024];
    int i = blockIdx.x * 1024 + threadIdx.x;
    int v = (i < n) ? g_deg[i] : 0;
    if (i < n) g_dis[i] = rsqrtf((float)(v + 1));   // +1 self loop
    s[threadIdx.x] = v;
    __syncthreads();
    for (int off = 1; off < 1024; off <<= 1) {
        int t = (threadIdx.x >= off) ? s[threadIdx.x - off] : 0;
        __syncthreads();
        s[threadIdx.x] += t;
        __syncthreads();
    }
    if (i < n) g_rowptr[i + 1] = s[threadIdx.x];
    if (threadIdx.x == 1023) g_bsum[blockIdx.x] = s[1023];
}

__global__ void k_scan2(int nb) {
    if (threadIdx.x == 0 && blockIdx.x == 0) {
        int acc = 0;
        for (int b = 0; b < nb; b++) { int t = g_bsum[b]; g_bsum[b] = acc; acc += t; }
    }
}

__global__ void k_scan3(int n) {
    int i = blockIdx.x * 1024 + threadIdx.x;
    if (i < n) {
        int v = g_rowptr[i + 1] + g_bsum[blockIdx.x];
        g_rowptr[i + 1] = v;
    }
    if (i == 0) g_rowptr[0] = 0;
}

__global__ void k_cursor(int n) {
    int i = blockIdx.x * blockDim.x + threadIdx.x;
    if (i < n) g_cursor[i] = g_rowptr[i];
}

__global__ void k_fill(int E) {
    int i = blockIdx.x * blockDim.x + threadIdx.x;
    if (i < E) {
        int p = atomicAdd(&g_cursor[g_dst[i]], 1);
        g_col[p] = g_src[i];
    }
}

// ---------------- 3-wide ops ----------------
__global__ void k_scale3(const float* __restrict__ in, float* __restrict__ out, int n) {
    int i = blockIdx.x * blockDim.x + threadIdx.x;
    if (i < n * 3) out[i] = in[i] * g_dis[i / 3];
}

__global__ void k_agg3(const float* __restrict__ in, float* __restrict__ out,
                       const float* __restrict__ bias, int n) {
    int node = blockIdx.x * blockDim.x + threadIdx.x;
    if (node >= n) return;
    float a0 = in[node * 3 + 0], a1 = in[node * 3 + 1], a2 = in[node * 3 + 2];
    int s = g_rowptr[node], e = g_rowptr[node + 1];
    for (int i = s; i < e; i++) {
        int c = g_col[i];
        a0 += in[c * 3 + 0];
        a1 += in[c * 3 + 1];
        a2 += in[c * 3 + 2];
    }
    float d = g_dis[node];
    a0 *= d; a1 *= d; a2 *= d;
    if (bias) { a0 += bias[0]; a1 += bias[1]; a2 += bias[2]; }
    out[node * 3 + 0] = a0;
    out[node * 3 + 1] = a1;
    out[node * 3 + 2] = a2;
}

__global__ void k_gemm_in(const float* __restrict__ t3, const float* __restrict__ W0,
                          const float* __restrict__ b0, float* __restrict__ out, int n) {
    __shared__ float sw[3 * HD];
    __shared__ float sb[HD];
    int t = threadIdx.x;
    for (int i = t; i < 3 * HD; i += blockDim.x) sw[i] = W0[i];
    if (t < HD) sb[t] = b0[t];
    __syncthreads();
    int gid = blockIdx.x * blockDim.x + t;
    if (gid < n * HD) {
        int node = gid >> 7, j = gid & 127;
        float p0 = t3[node * 3 + 0], p1 = t3[node * 3 + 1], p2 = t3[node * 3 + 2];
        float v = p0 * sw[j] + p1 * sw[HD + j] + p2 * sw[2 * HD + j] + sb[j];
        out[gid] = v / (1.0f + __expf(-v));
    }
}

__global__ void k_gemm_out(const float* __restrict__ X, const float* __restrict__ W4,
                           float* __restrict__ Hs, int n) {
    int warp = (blockIdx.x * blockDim.x + threadIdx.x) >> 5;
    int lane = threadIdx.x & 31;
    if (warp >= n) return;
    float4 x = ((const float4*)X)[warp * 32 + lane];
    int k = lane * 4;
    float a0 = x.x * W4[(k + 0) * 3 + 0] + x.y * W4[(k + 1) * 3 + 0] +
               x.z * W4[(k + 2) * 3 + 0] + x.w * W4[(k + 3) * 3 + 0];
    float a1 = x.x * W4[(k + 0) * 3 + 1] + x.y * W4[(k + 1) * 3 + 1] +
               x.z * W4[(k + 2) * 3 + 1] + x.w * W4[(k + 3) * 3 + 1];
    float a2 = x.x * W4[(k + 0) * 3 + 2] + x.y * W4[(k + 1) * 3 + 2] +
               x.z * W4[(k + 2) * 3 + 2] + x.w * W4[(k + 3) * 3 + 2];
    for (int off = 16; off; off >>= 1) {
        a0 += __shfl_xor_sync(0xFFFFFFFF, a0, off);
        a1 += __shfl_xor_sync(0xFFFFFFFF, a1, off);
        a2 += __shfl_xor_sync(0xFFFFFFFF, a2, off);
    }
    if (lane == 0) {
        float d = g_dis[warp];
        Hs[warp * 3 + 0] = a0 * d;
        Hs[warp * 3 + 1] = a1 * d;
        Hs[warp * 3 + 2] = a2 * d;
    }
}

// ---------------- tensor-core hidden GEMM: H = diag(dis)·X @ W ----------------
// Markidis fp16 split: X*dis = Ah+Al, W = Bh+Bl; C += Ah·Bh + Al·Bh + Ah·Bl.
// Block = 128x128 output tile, 8 warps, warp tile 32x64 (2x4 wmma 16x16 frags).
// dis folded into A conversion -> accumulators store straight to gmem.
__global__ __launch_bounds__(256) void k_gemm128_tc(const float* __restrict__ X,
                                                    const float* __restrict__ W,
                                                    float* __restrict__ Hout) {
    __shared__ __align__(16) __half sAh[128 * 16];
    __shared__ __align__(16) __half sAl[128 * 16];
    __shared__ __align__(16) __half sBh[16 * 128];
    __shared__ __align__(16) __half sBl[16 * 128];

    int m0 = blockIdx.x * 128;
    int t = threadIdx.x;
    int warp = t >> 5;
    int wm = warp >> 1;          // 0..3 : row group (32 rows)
    int wn = warp & 1;           // 0..1 : col group (64 cols)

    wmma::fragment<wmma::accumulator, 16, 16, 16, float> c[2][4];
#pragma unroll
    for (int i = 0; i < 2; i++)
#pragma unroll
        for (int j = 0; j < 4; j++) wmma::fill_fragment(c[i][j], 0.0f);

    for (int k0 = 0; k0 < HD; k0 += 16) {
        // stage A tile (128x16) with dis folded in, split to hi/lo halves
#pragma unroll
        for (int q = 0; q < 2; q++) {
            int f = t + q * 256;          // 0..511 float4 slots
            int row = f >> 2;             // 0..127
            int c4 = f & 3;               // 0..3
            int gr = m0 + row;            // < NPAD always
            float d = g_dis[gr];
            float4 v = *(const float4*)(X + gr * HD + k0 + c4 * 4);
            float x0 = v.x * d, x1 = v.y * d, x2 = v.z * d, x3 = v.w * d;
            __half h0 = __float2half_rn(x0), h1 = __float2half_rn(x1);
            __half h2 = __float2half_rn(x2), h3 = __float2half_rn(x3);
            int base = row * 16 + c4 * 4;
            sAh[base + 0] = h0; sAh[base + 1] = h1; sAh[base + 2] = h2; sAh[base + 3] = h3;
            sAl[base + 0] = __float2half_rn(x0 - __half2float(h0));
            sAl[base + 1] = __float2half_rn(x1 - __half2float(h1));
            sAl[base + 2] = __float2half_rn(x2 - __half2float(h2));
            sAl[base + 3] = __float2half_rn(x3 - __half2float(h3));
        }
        // stage B tile (16x128)
#pragma unroll
        for (int q = 0; q < 2; q++) {
            int f = t + q * 256;
            int kr = f >> 5;              // 0..15
            int cc = (f & 31) * 4;        // 0..124
            float4 v = *(const float4*)(W + (k0 + kr) * HD + cc);
            __half h0 = __float2half_rn(v.x), h1 = __float2half_rn(v.y);
            __half h2 = __float2half_rn(v.z), h3 = __float2half_rn(v.w);
            int base = kr * 128 + cc;
            sBh[base + 0] = h0; sBh[base + 1] = h1; sBh[base + 2] = h2; sBh[base + 3] = h3;
            sBl[base + 0] = __float2half_rn(v.x - __half2float(h0));
            sBl[base + 1] = __float2half_rn(v.y - __half2float(h1));
            sBl[base + 2] = __float2half_rn(v.z - __half2float(h2));
            sBl[base + 3] = __float2half_rn(v.w - __half2float(h3));
        }
        __syncthreads();

        wmma::fragment<wmma::matrix_a, 16, 16, 16, __half, wmma::row_major> aH[2], aL[2];
        wmma::fragment<wmma::matrix_b, 16, 16, 16, __half, wmma::row_major> bH[4], bL[4];
#pragma unroll
        for (int i = 0; i < 2; i++) {
            wmma::load_matrix_sync(aH[i], &sAh[(wm * 32 + i * 16) * 16], 16);
            wmma::load_matrix_sync(aL[i], &sAl[(wm * 32 + i * 16) * 16], 16);
        }
#pragma unroll
        for (int j = 0; j < 4; j++) {
            wmma::load_matrix_sync(bH[j], &sBh[wn * 64 + j * 16], 128);
            wmma::load_matrix_sync(bL[j], &sBl[wn * 64 + j * 16], 128);
        }
#pragma unroll
        for (int i = 0; i < 2; i++)
#pragma unroll
            for (int j = 0; j < 4; j++) {
                wmma::mma_sync(c[i][j], aH[i], bH[j], c[i][j]);
                wmma::mma_sync(c[i][j], aL[i], bH[j], c[i][j]);
                wmma::mma_sync(c[i][j], aH[i], bL[j], c[i][j]);
            }
        __syncthreads();
    }

    // store: rows m0+wm*32+i*16 .. +16 (always < NPAD; padding rows never read)
#pragma unroll
    for (int i = 0; i < 2; i++)
#pragma unroll
        for (int j = 0; j < 4; j++) {
            float* dst = Hout + (m0 + wm * 32 + i * 16) * HD + wn * 64 + j * 16;
            wmma::store_matrix_sync(dst, c[i][j], HD, wmma::mem_row_major);
        }
}

// ---------------- 128-wide aggregation: warp per node ----------------
__global__ void k_agg128(const float* __restrict__ hs, const float* __restrict__ bias,
                         float* __restrict__ out, int n) {
    int warp = (blockIdx.x * blockDim.x + threadIdx.x) >> 5;
    int lane = threadIdx.x & 31;
    if (warp >= n) return;
    const float4* hs4 = (const float4*)hs;
    float4 acc = hs4[warp * 32 + lane];   // self loop (hs = h*dis)
    int s = g_rowptr[warp], e = g_rowptr[warp + 1];
    int i = s;
    for (; i + 4 <= e; i += 4) {
        int c0 = g_col[i], c1 = g_col[i + 1], c2 = g_col[i + 2], c3 = g_col[i + 3];
        float4 v0 = hs4[c0 * 32 + lane];
        float4 v1 = hs4[c1 * 32 + lane];
        float4 v2 = hs4[c2 * 32 + lane];
        float4 v3 = hs4[c3 * 32 + lane];
        acc.x += v0.x + v1.x + v2.x + v3.x;
        acc.y += v0.y + v1.y + v2.y + v3.y;
        acc.z += v0.z + v1.z + v2.z + v3.z;
        acc.w += v0.w + v1.w + v2.w + v3.w;
    }
    for (; i < e; i++) {
        int c = g_col[i];
        float4 v = hs4[c * 32 + lane];
        acc.x += v.x; acc.y += v.y; acc.z += v.z; acc.w += v.w;
    }
    float d = g_dis[warp];
    float4 b = ((const float4*)bias)[lane];
    float4 r;
    r.x = acc.x * d + b.x;
    r.y = acc.y * d + b.y;
    r.z = acc.z * d + b.z;
    r.w = acc.w * d + b.w;
    r.x = r.x / (1.0f + __expf(-r.x));
    r.y = r.y / (1.0f + __expf(-r.y));
    r.z = r.z / (1.0f + __expf(-r.z));
    r.w = r.w / (1.0f + __expf(-r.w));
    ((float4*)out)[warp * 32 + lane] = r;
}

// ---------------- host launch ----------------
extern "C" void kernel_launch(void* const* d_in, const int* in_sizes, int n_in,
                              void* d_out, int out_size) {
    const float* pos = (const float*)d_in[0];
    const int* ei_words = (const int*)d_in[1];
    const float* W[5]; const float* B[5];
    for (int l = 0; l < 5; l++) {
        W[l] = (const float*)d_in[2 + 2 * l];
        B[l] = (const float*)d_in[3 + 2 * l];
    }
    int N = in_sizes[0] / 3;        // 50000
    int E = in_sizes[1] / 2;        // 1000000

    float *bufA, *bufB, *s1, *s2;
    cudaGetSymbolAddress((void**)&bufA, g_bufA);
    cudaGetSymbolAddress((void**)&bufB, g_bufB);
    cudaGetSymbolAddress((void**)&s1, g_s1);
    cudaGetSymbolAddress((void**)&s2, g_s2);

    int NB = (N + 1023) / 1024;

    // canonicalize edges + degrees (fused)
    k_detect<<<1, 32>>>(ei_words, E);
    k_deg_zero<<<(N + 255) / 256, 256>>>(N);
    k_convert<<<(E + 255) / 256, 256>>>(ei_words, E);

    // CSR build
    k_scan1<<<NB, 1024>>>(N);
    k_scan2<<<1, 32>>>(NB);
    k_scan3<<<NB, 1024>>>(N);
    k_cursor<<<NB, 1024>>>(N);
    k_fill<<<(E + 255) / 256, 256>>>(E);

    // layer 0: aggregate pos (3-wide) first, then dense W0 + bias + silu
    k_scale3<<<(3 * N + 255) / 256, 256>>>(pos, s1, N);
    k_agg3<<<(N + 255) / 256, 256>>>(s1, s2, nullptr, N);
    k_gemm_in<<<(N * HD + 255) / 256, 256>>>(s2, W[0], B[0], bufA, N);

    // layers 1..3: tensor-core GEMM (dis folded) then aggregation + bias + silu
    int gemm_blocks = (N + 127) / 128;   // 391
    int agg_blocks = (N * 32 + 255) / 256;
    for (int l = 1; l <= 3; l++) {
        k_gemm128_tc<<<gemm_blocks, 256>>>(bufA, W[l], bufB);
        k_agg128<<<agg_blocks, 256>>>(bufB, B[l], bufA, N);
    }

    // layer 4: dense to 3-wide first, then 3-wide aggregation + bias
    k_gemm_out<<<agg_blocks, 256>>>(bufA, W[4], s1, N);
    k_agg3<<<(N + 255) / 256, 256>>>(s1, (float*)d_out, B[4], N);
}

// round 5
// speedup vs baseline: 1.3061x; 1.1241x over previous
#include <cuda_runtime.h>
#include <cuda_fp16.h>
#include <mma.h>

using namespace nvcuda;

#define NMAX 50000
#define NPAD 50176          // 392*128 padding so GEMM tiles stay in-bounds
#define EMAX 1000000
#define HD   128

// ---------------- device scratch (no allocation allowed) ----------------
__device__ __align__(16) float  g_bufA[NPAD * HD];    // x~ = dis*silu activations (fp32; padding stays 0)
__device__ __align__(16) __half g_hs[NPAD * HD];      // messages hs = x~ @ W (fp16)
__device__ __align__(16) float  g_s1[NMAX * 3 + 4];
__device__ __align__(16) float  g_s2[NMAX * 3 + 4];
__device__ __align__(16) float  g_dis[NPAD];
__device__ __align__(16) int    g_deg[NMAX];
__device__ __align__(16) int    g_rowptr[NMAX + 1];
__device__ __align__(16) int    g_cursor[NMAX];
__device__ __align__(16) int    g_col[EMAX];
__device__ __align__(16) int    g_src[EMAX];
__device__ __align__(16) int    g_dst[EMAX];
__device__ __align__(16) int    g_bsum[64];
__device__ int g_is64;

// ---------------- edge dtype detection (warp-parallel) ----------------
// int64 little-endian with values < 2^31 => odd 32-bit words of src region are 0.
__global__ void k_detect(const int* __restrict__ w, int E) {
    int lane = threadIdx.x & 31;
    int lim = 2 * E;
    int v = 0;
    for (int q = 0; q < 4; q++) {
        int idx = 1 + 2 * (lane + q * 32);
        if (idx < lim) v |= w[idx];
    }
    int any = __any_sync(0xFFFFFFFF, v != 0);
    if (lane == 0) g_is64 = any ? 0 : 1;
}

__global__ void k_deg_zero(int n) {
    int i = blockIdx.x * blockDim.x + threadIdx.x;
    if (i < n) g_deg[i] = 0;
}

// convert + degree count fused
__global__ void k_convert(const int* __restrict__ w, int E) {
    int i = blockIdx.x * blockDim.x + threadIdx.x;
    if (i >= E) return;
    int s, d;
    if (g_is64) {
        s = w[2 * i];
        d = w[2 * E + 2 * i];
    } else {
        s = w[i];
        d = w[E + i];
    }
    g_src[i] = s;
    g_dst[i] = d;
    atomicAdd(&g_deg[d], 1);
}

// ---------------- CSR build ----------------
__global__ void k_scan1(int n) {
    __shared__ int s[1024];
    int i = blockIdx.x * 1024 + threadIdx.x;
    int v = (i < n) ? g_deg[i] : 0;
    if (i < n) g_dis[i] = rsqrtf((float)(v + 1));   // +1 self loop
    s[threadIdx.x] = v;
    __syncthreads();
    for (int off = 1; off < 1024; off <<= 1) {
        int t = (threadIdx.x >= off) ? s[threadIdx.x - off] : 0;
        __syncthreads();
        s[threadIdx.x] += t;
        __syncthreads();
    }
    if (i < n) g_rowptr[i + 1] = s[threadIdx.x];
    if (threadIdx.x == 1023) g_bsum[blockIdx.x] = s[1023];
}

__global__ void k_scan2(int nb) {
    if (threadIdx.x == 0 && blockIdx.x == 0) {
        int acc = 0;
        for (int b = 0; b < nb; b++) { int t = g_bsum[b]; g_bsum[b] = acc; acc += t; }
    }
}

// finalize rowptr + init cursor (fused)
__global__ void k_scan3(int n) {
    int i = blockIdx.x * 1024 + threadIdx.x;
    if (i < n) {
        int v = g_rowptr[i + 1] + g_bsum[blockIdx.x];
        g_rowptr[i + 1] = v;
        if (i + 1 < n) g_cursor[i + 1] = v;
    }
    if (i == 0) { g_rowptr[0] = 0; g_cursor[0] = 0; }
}

__global__ void k_fill(int E) {
    int i = blockIdx.x * blockDim.x + threadIdx.x;
    if (i < E) {
        int p = atomicAdd(&g_cursor[g_dst[i]], 1);
        g_col[p] = g_src[i];
    }
}

// ---------------- 3-wide ops ----------------
__global__ void k_scale3(const float* __restrict__ in, float* __restrict__ out, int n) {
    int i = blockIdx.x * blockDim.x + threadIdx.x;
    if (i < n * 3) out[i] = in[i] * g_dis[i / 3];
}

__global__ void k_agg3(const float* __restrict__ in, float* __restrict__ out,
                       const float* __restrict__ bias, int n) {
    int node = blockIdx.x * blockDim.x + threadIdx.x;
    if (node >= n) return;
    float a0 = in[node * 3 + 0], a1 = in[node * 3 + 1], a2 = in[node * 3 + 2];
    int s = g_rowptr[node], e = g_rowptr[node + 1];
    for (int i = s; i < e; i++) {
        int c = g_col[i];
        a0 += in[c * 3 + 0];
        a1 += in[c * 3 + 1];
        a2 += in[c * 3 + 2];
    }
    float d = g_dis[node];
    a0 *= d; a1 *= d; a2 *= d;
    if (bias) { a0 += bias[0]; a1 += bias[1]; a2 += bias[2]; }
    out[node * 3 + 0] = a0;
    out[node * 3 + 1] = a1;
    out[node * 3 + 2] = a2;
}

// x~ = dis * silu(t3 @ W0 + b0)
__global__ void k_gemm_in(const float* __restrict__ t3, const float* __restrict__ W0,
                          const float* __restrict__ b0, float* __restrict__ out, int n) {
    __shared__ float sw[3 * HD];
    __shared__ float sb[HD];
    int t = threadIdx.x;
    for (int i = t; i < 3 * HD; i += blockDim.x) sw[i] = W0[i];
    if (t < HD) sb[t] = b0[t];
    __syncthreads();
    int gid = blockIdx.x * blockDim.x + t;
    if (gid < n * HD) {
        int node = gid >> 7, j = gid & 127;
        float p0 = t3[node * 3 + 0], p1 = t3[node * 3 + 1], p2 = t3[node * 3 + 2];
        float v = p0 * sw[j] + p1 * sw[HD + j] + p2 * sw[2 * HD + j] + sb[j];
        out[gid] = g_dis[node] * (v / (1.0f + __expf(-v)));
    }
}

// hs3 = x~ @ W4  (warp per node; dis already folded into x~)
__global__ void k_gemm_out(const float* __restrict__ X, const float* __restrict__ W4,
                           float* __restrict__ Hs, int n) {
    int warp = (blockIdx.x * blockDim.x + threadIdx.x) >> 5;
    int lane = threadIdx.x & 31;
    if (warp >= n) return;
    float4 x = ((const float4*)X)[warp * 32 + lane];
    int k = lane * 4;
    float a0 = x.x * W4[(k + 0) * 3 + 0] + x.y * W4[(k + 1) * 3 + 0] +
               x.z * W4[(k + 2) * 3 + 0] + x.w * W4[(k + 3) * 3 + 0];
    float a1 = x.x * W4[(k + 0) * 3 + 1] + x.y * W4[(k + 1) * 3 + 1] +
               x.z * W4[(k + 2) * 3 + 1] + x.w * W4[(k + 3) * 3 + 1];
    float a2 = x.x * W4[(k + 0) * 3 + 2] + x.y * W4[(k + 1) * 3 + 2] +
               x.z * W4[(k + 2) * 3 + 2] + x.w * W4[(k + 3) * 3 + 2];
    for (int off = 16; off; off >>= 1) {
        a0 += __shfl_xor_sync(0xFFFFFFFF, a0, off);
        a1 += __shfl_xor_sync(0xFFFFFFFF, a1, off);
        a2 += __shfl_xor_sync(0xFFFFFFFF, a2, off);
    }
    if (lane == 0) {
        Hs[warp * 3 + 0] = a0;
        Hs[warp * 3 + 1] = a1;
        Hs[warp * 3 + 2] = a2;
    }
}

// ---------------- tensor-core hidden GEMM: hs = x~ @ W (fp16 out) ----------------
// Markidis split on both operands; fp32 accumulate; output converted to fp16
// via a 16x16 per-warp smem bounce (message precision 2.4e-4 is plenty).
__global__ __launch_bounds__(256) void k_gemm128_tc(const float* __restrict__ X,
                                                    const float* __restrict__ W,
                                                    __half* __restrict__ Hout) {
    __shared__ __align__(16) __half sAh[128 * 16];
    __shared__ __align__(16) __half sAl[128 * 16];
    __shared__ __align__(16) __half sBh[16 * 128];
    __shared__ __align__(16) __half sBl[16 * 128];
    __shared__ __align__(16) float  sOut[8][16 * 16];   // per-warp store bounce

    int m0 = blockIdx.x * 128;
    int t = threadIdx.x;
    int warp = t >> 5;
    int lane = t & 31;
    int wm = warp >> 1;          // 0..3 : 32-row group
    int wn = warp & 1;           // 0..1 : 64-col group

    wmma::fragment<wmma::accumulator, 16, 16, 16, float> c[2][4];
#pragma unroll
    for (int i = 0; i < 2; i++)
#pragma unroll
        for (int j = 0; j < 4; j++) wmma::fill_fragment(c[i][j], 0.0f);

    for (int k0 = 0; k0 < HD; k0 += 16) {
#pragma unroll
        for (int q = 0; q < 2; q++) {
            int f = t + q * 256;          // 0..511 float4 slots
            int row = f >> 2;
            int c4 = f & 3;
            int gr = m0 + row;
            float4 v = *(const float4*)(X + gr * HD + k0 + c4 * 4);
            __half h0 = __float2half_rn(v.x), h1 = __float2half_rn(v.y);
            __half h2 = __float2half_rn(v.z), h3 = __float2half_rn(v.w);
            int base = row * 16 + c4 * 4;
            sAh[base + 0] = h0; sAh[base + 1] = h1; sAh[base + 2] = h2; sAh[base + 3] = h3;
            sAl[base + 0] = __float2half_rn(v.x - __half2float(h0));
            sAl[base + 1] = __float2half_rn(v.y - __half2float(h1));
            sAl[base + 2] = __float2half_rn(v.z - __half2float(h2));
            sAl[base + 3] = __float2half_rn(v.w - __half2float(h3));
        }
#pragma unroll
        for (int q = 0; q < 2; q++) {
            int f = t + q * 256;
            int kr = f >> 5;
            int cc = (f & 31) * 4;
            float4 v = *(const float4*)(W + (k0 + kr) * HD + cc);
            __half h0 = __float2half_rn(v.x), h1 = __float2half_rn(v.y);
            __half h2 = __float2half_rn(v.z), h3 = __float2half_rn(v.w);
            int base = kr * 128 + cc;
            sBh[base + 0] = h0; sBh[base + 1] = h1; sBh[base + 2] = h2; sBh[base + 3] = h3;
            sBl[base + 0] = __float2half_rn(v.x - __half2float(h0));
            sBl[base + 1] = __float2half_rn(v.y - __half2float(h1));
            sBl[base + 2] = __float2half_rn(v.z - __half2float(h2));
            sBl[base + 3] = __float2half_rn(v.w - __half2float(h3));
        }
        __syncthreads();

        wmma::fragment<wmma::matrix_a, 16, 16, 16, __half, wmma::row_major> aH[2], aL[2];
        wmma::fragment<wmma::matrix_b, 16, 16, 16, __half, wmma::row_major> bH[4], bL[4];
#pragma unroll
        for (int i = 0; i < 2; i++) {
            wmma::load_matrix_sync(aH[i], &sAh[(wm * 32 + i * 16) * 16], 16);
            wmma::load_matrix_sync(aL[i], &sAl[(wm * 32 + i * 16) * 16], 16);
        }
#pragma unroll
        for (int j = 0; j < 4; j++) {
            wmma::load_matrix_sync(bH[j], &sBh[wn * 64 + j * 16], 128);
            wmma::load_matrix_sync(bL[j], &sBl[wn * 64 + j * 16], 128);
        }
#pragma unroll
        for (int i = 0; i < 2; i++)
#pragma unroll
            for (int j = 0; j < 4; j++) {
                wmma::mma_sync(c[i][j], aH[i], bH[j], c[i][j]);
                wmma::mma_sync(c[i][j], aL[i], bH[j], c[i][j]);
                wmma::mma_sync(c[i][j], aH[i], bL[j], c[i][j]);
            }
        __syncthreads();
    }

    // fp32 fragment -> fp16 gmem via per-warp smem bounce
#pragma unroll
    for (int i = 0; i < 2; i++)
#pragma unroll
        for (int j = 0; j < 4; j++) {
            wmma::store_matrix_sync(&sOut[warp][0], c[i][j], 16, wmma::mem_row_major);
            __syncwarp();
            int r = lane >> 1;                 // 0..15
            int c8 = (lane & 1) * 8;           // 0 or 8
            const float* srcp = &sOut[warp][r * 16 + c8];
            __half2 o[4];
#pragma unroll
            for (int q = 0; q < 4; q++)
                o[q] = __floats2half2_rn(srcp[2 * q], srcp[2 * q + 1]);
            __half* dst = Hout + (m0 + wm * 32 + i * 16 + r) * HD + wn * 64 + j * 16 + c8;
            *(uint4*)dst = *(uint4*)o;
            __syncwarp();
        }
}

// ---------------- 128-wide aggregation (fp16 gather): warp per node ----------------
// x~out[n] = dis[n] * silu( dis[n]*(hs[n] + sum hs[src]) + b )
__global__ void k_agg128(const __half* __restrict__ hs, const float* __restrict__ bias,
                         float* __restrict__ out, int n) {
    int warp = (blockIdx.x * blockDim.x + threadIdx.x) >> 5;
    int lane = threadIdx.x & 31;
    if (warp >= n) return;
    const uint2* hsv = (const uint2*)hs;       // 2x half2 = 4 features per lane
    float4 acc;
    {
        uint2 u = hsv[warp * 32 + lane];       // self loop
        float2 p0 = __half22float2(*(__half2*)&u.x);
        float2 p1 = __half22float2(*(__half2*)&u.y);
        acc = make_float4(p0.x, p0.y, p1.x, p1.y);
    }
    int s = g_rowptr[warp], e = g_rowptr[warp + 1];
    int i = s;
    for (; i + 4 <= e; i += 4) {
        int c0 = g_col[i], c1 = g_col[i + 1], c2 = g_col[i + 2], c3 = g_col[i + 3];
        uint2 u0 = hsv[c0 * 32 + lane];
        uint2 u1 = hsv[c1 * 32 + lane];
        uint2 u2 = hsv[c2 * 32 + lane];
        uint2 u3 = hsv[c3 * 32 + lane];
        float2 a0 = __half22float2(*(__half2*)&u0.x), b0 = __half22float2(*(__half2*)&u0.y);
        float2 a1 = __half22float2(*(__half2*)&u1.x), b1 = __half22float2(*(__half2*)&u1.y);
        float2 a2 = __half22float2(*(__half2*)&u2.x), b2 = __half22float2(*(__half2*)&u2.y);
        float2 a3 = __half22float2(*(__half2*)&u3.x), b3 = __half22float2(*(__half2*)&u3.y);
        acc.x += a0.x + a1.x + a2.x + a3.x;
        acc.y += a0.y + a1.y + a2.y + a3.y;
        acc.z += b0.x + b1.x + b2.x + b3.x;
        acc.w += b0.y + b1.y + b2.y + b3.y;
    }
    for (; i < e; i++) {
        int c = g_col[i];
        uint2 u = hsv[c * 32 + lane];
        float2 p0 = __half22float2(*(__half2*)&u.x);
        float2 p1 = __half22float2(*(__half2*)&u.y);
        acc.x += p0.x; acc.y += p0.y; acc.z += p1.x; acc.w += p1.y;
    }
    float d = g_dis[warp];
    float4 b = ((const float4*)bias)[lane];
    float4 r;
    r.x = acc.x * d + b.x;
    r.y = acc.y * d + b.y;
    r.z = acc.z * d + b.z;
    r.w = acc.w * d + b.w;
    r.x = d * (r.x / (1.0f + __expf(-r.x)));
    r.y = d * (r.y / (1.0f + __expf(-r.y)));
    r.z = d * (r.z / (1.0f + __expf(-r.z)));
    r.w = d * (r.w / (1.0f + __expf(-r.w)));
    ((float4*)out)[warp * 32 + lane] = r;
}

// ---------------- host launch ----------------
extern "C" void kernel_launch(void* const* d_in, const int* in_sizes, int n_in,
                              void* d_out, int out_size) {
    const float* pos = (const float*)d_in[0];
    const int* ei_words = (const int*)d_in[1];
    const float* W[5]; const float* B[5];
    for (int l = 0; l < 5; l++) {
        W[l] = (const float*)d_in[2 + 2 * l];
        B[l] = (const float*)d_in[3 + 2 * l];
    }
    int N = in_sizes[0] / 3;        // 50000
    int E = in_sizes[1] / 2;        // 1000000

    float *bufA, *s1, *s2;
    __half* hsbuf;
    cudaGetSymbolAddress((void**)&bufA, g_bufA);
    cudaGetSymbolAddress((void**)&hsbuf, g_hs);
    cudaGetSymbolAddress((void**)&s1, g_s1);
    cudaGetSymbolAddress((void**)&s2, g_s2);

    int NB = (N + 1023) / 1024;

    // canonicalize edges + degrees
    k_detect<<<1, 32>>>(ei_words, E);
    k_deg_zero<<<(N + 255) / 256, 256>>>(N);
    k_convert<<<(E + 255) / 256, 256>>>(ei_words, E);

    // CSR build
    k_scan1<<<NB, 1024>>>(N);
    k_scan2<<<1, 32>>>(NB);
    k_scan3<<<NB, 1024>>>(N);
    k_fill<<<(E + 255) / 256, 256>>>(E);

    // layer 0: 3-wide aggregate then dense W0 (+bias, silu, dis fold)
    k_scale3<<<(3 * N + 255) / 256, 256>>>(pos, s1, N);
    k_agg3<<<(N + 255) / 256, 256>>>(s1, s2, nullptr, N);
    k_gemm_in<<<(N * HD + 255) / 256, 256>>>(s2, W[0], B[0], bufA, N);

    // layers 1..3: TC GEMM (fp16 out) then fp16-gather aggregation
    int gemm_blocks = (N + 127) / 128;   // 391
    int agg_blocks = (N * 32 + 255) / 256;
    for (int l = 1; l <= 3; l++) {
        k_gemm128_tc<<<gemm_blocks, 256>>>(bufA, W[l], hsbuf);
        k_agg128<<<agg_blocks, 256>>>(hsbuf, B[l], bufA, N);
    }

    // layer 4: dense to 3-wide, then 3-wide aggregation + bias -> out
    k_gemm_out<<<agg_blocks, 256>>>(bufA, W[4], s1, N);
    k_agg3<<<(N + 255) / 256, 256>>>(s1, (float*)d_out, B[4], N);
}